// round 8
// baseline (speedup 1.0000x reference)
#include <cuda_runtime.h>
#include <cuda_bf16.h>
#include <cstdint>

#define LL 512
#define DD 128
#define NCTA 128

// ---------------- scratch globals ----------------
__device__ float g_keep[LL];
__device__ float g_seq[LL * DD];
__device__ float g_Q[LL * DD];
__device__ float g_qp[LL * DD];
__device__ float g_kp[LL * DD];
__device__ float g_vp[LL * DD];
__device__ float g_x[LL * DD];
__device__ float g_h[LL * DD];
__device__ float g_twlog[2 * LL * LL];
__device__ __nv_bfloat16 g_Bimg[2 * 128 * 128];  // [s][n][k] = Wt[s][k][n]

__device__ unsigned g_bar_count;
__device__ volatile unsigned g_bar_gen;

__device__ __forceinline__ void grid_barrier() {
    __syncthreads();
    if (threadIdx.x == 0) {
        __threadfence();
        unsigned gen = g_bar_gen;
        if (atomicAdd(&g_bar_count, 1u) == NCTA - 1) {
            atomicExch(&g_bar_count, 0u);
            __threadfence();
            g_bar_gen = gen + 1u;
        } else {
            while (g_bar_gen == gen) __nanosleep(64);
        }
        __threadfence();
    }
    __syncthreads();
}

__device__ __forceinline__ uint32_t smem_to_u32(const void* p) {
    uint32_t a;
    asm("{ .reg .u64 t; cvta.to.shared.u64 t, %1; cvt.u32.u64 %0, t; }" : "=r"(a) : "l"(p));
    return a;
}
__device__ __forceinline__ void ldmatrix_x4(uint32_t* r, uint32_t addr) {
    asm volatile("ldmatrix.sync.aligned.m8n8.x4.shared.b16 {%0,%1,%2,%3}, [%4];"
                 : "=r"(r[0]), "=r"(r[1]), "=r"(r[2]), "=r"(r[3]) : "r"(addr));
}
__device__ __forceinline__ void mma16816(float* c, const uint32_t* a, uint32_t b0, uint32_t b1) {
    asm volatile(
        "mma.sync.aligned.m16n8k16.row.col.f32.bf16.bf16.f32 "
        "{%0,%1,%2,%3}, {%4,%5,%6,%7}, {%8,%9}, {%0,%1,%2,%3};"
        : "+f"(c[0]), "+f"(c[1]), "+f"(c[2]), "+f"(c[3])
        : "r"(a[0]), "r"(a[1]), "r"(a[2]), "r"(a[3]), "r"(b0), "r"(b1));
}

// ---------------- prep: keep + masked seqs + B images, one kernel -----------
__global__ void prep_all_kernel(const int* __restrict__ logs, const float* __restrict__ seqs,
                                const float* __restrict__ Wt) {
    int i = blockIdx.x * 256 + threadIdx.x;  // 65536
    if (i < LL) g_keep[i] = (logs[i] == 0) ? 0.0f : 1.0f;
    int row = i >> 7;
    float k = (logs[row] == 0) ? 0.0f : 1.0f;
    g_seq[i] = seqs[i] * k;
    if (i < 32768) {
        int s = i >> 14, e = i & 16383;
        int n = e >> 7, kk = e & 127;
        g_Bimg[i] = __float2bfloat16(Wt[s * 16384 + kk * 128 + n]);
    }
}

// ---------------- big fused time-bias kernel (HMMA mma.sync) ----------------
#define TW_SA   0
#define TW_SB   34816
#define TW_SSC  (TW_SB + 2 * 34816)      // 104448
#define TW_SMEM (TW_SSC + 2064)          // 106512

__global__ void __launch_bounds__(256, 2)
twbias_kernel(const float* __restrict__ T, const float* __restrict__ bt,
              const float* __restrict__ Wtp, const float* __restrict__ btp) {
    extern __shared__ char smem[];
    uint32_t sb = smem_to_u32(smem);
    int tid = threadIdx.x;
    float* sc = (float*)(smem + TW_SSC);

    {   // stage B images (padded rows, 272B stride)
        const uint4* src = (const uint4*)g_Bimg;
        for (int i = tid; i < 4096; i += 256) {
            int e = i * 8;
            int s = e >> 14, n = (e >> 7) & 127, k = e & 127;
            *(uint4*)(smem + TW_SB + s * 34816 + n * 272 + k * 2) = src[i];
        }
    }
    if (tid < 128) {
        sc[tid]       = bt[tid];
        sc[128 + tid] = bt[128 + tid];
        sc[256 + tid] = Wtp[tid];
        sc[384 + tid] = Wtp[128 + tid];
    }
    if (tid == 0) { sc[512] = btp[0]; sc[513] = btp[1]; }

    {   // A tile: 128 rows x 128 fp32 -> bf16, stride 272B
        size_t r0 = (size_t)blockIdx.x * 128;
        const float4* Tb = (const float4*)(T + r0 * 128);
#pragma unroll
        for (int i = 0; i < 16; i++) {
            int c = tid + 256 * i;
            int r = c >> 5, kc = (c & 31) << 2;
            float4 a = Tb[c];
            __nv_bfloat162 lo = __floats2bfloat162_rn(a.x, a.y);
            __nv_bfloat162 hi = __floats2bfloat162_rn(a.z, a.w);
            uint2 u;
            u.x = *reinterpret_cast<uint32_t*>(&lo);
            u.y = *reinterpret_cast<uint32_t*>(&hi);
            *(uint2*)(smem + TW_SA + r * 272 + kc * 2) = u;
        }
    }
    __syncthreads();

    int lane = tid & 31, w = tid >> 5;
    int s = w >> 2, mrow0 = (w & 3) * 32;
    int l8 = lane & 7, gq = lane >> 3;
    int arow = (gq & 1) * 8 + l8;
    int akoff = (gq >> 1) * 8;

    uint32_t a[2][8][4];
#pragma unroll
    for (int mt = 0; mt < 2; mt++)
#pragma unroll
        for (int kt = 0; kt < 8; kt++) {
            uint32_t addr = sb + TW_SA + (uint32_t)(mrow0 + mt * 16 + arow) * 272
                          + (uint32_t)(kt * 16 + akoff) * 2;
            ldmatrix_x4(a[mt][kt], addr);
        }

    int bntl = gq >> 1;
    int bkoff = (gq & 1) * 8;
    uint32_t b_base = sb + TW_SB + (uint32_t)s * 34816;
    int qd = lane & 3;

    float accR[2][2] = {{0.f, 0.f}, {0.f, 0.f}};
#pragma unroll
    for (int ntp = 0; ntp < 8; ntp++) {
        float c[2][2][4];
#pragma unroll
        for (int i = 0; i < 2; i++)
#pragma unroll
            for (int j = 0; j < 2; j++)
#pragma unroll
                for (int t = 0; t < 4; t++) c[i][j][t] = 0.f;
#pragma unroll
        for (int kt = 0; kt < 8; kt++) {
            uint32_t baddr = b_base + (uint32_t)(ntp * 16 + bntl * 8 + l8) * 272
                           + (uint32_t)(kt * 16 + bkoff) * 2;
            uint32_t b[4];
            ldmatrix_x4(b, baddr);
            mma16816(c[0][0], a[0][kt], b[0], b[1]);
            mma16816(c[0][1], a[0][kt], b[2], b[3]);
            mma16816(c[1][0], a[1][kt], b[0], b[1]);
            mma16816(c[1][1], a[1][kt], b[2], b[3]);
        }
#pragma unroll
        for (int nh = 0; nh < 2; nh++) {
            int n0 = (ntp * 2 + nh) * 8 + 2 * qd;
            float bt0 = sc[s * 128 + n0],       bt1 = sc[s * 128 + n0 + 1];
            float wp0 = sc[256 + s * 128 + n0], wp1 = sc[256 + s * 128 + n0 + 1];
            accR[0][0] += fmaxf(c[0][nh][0] + bt0, 0.f) * wp0 + fmaxf(c[0][nh][1] + bt1, 0.f) * wp1;
            accR[0][1] += fmaxf(c[0][nh][2] + bt0, 0.f) * wp0 + fmaxf(c[0][nh][3] + bt1, 0.f) * wp1;
            accR[1][0] += fmaxf(c[1][nh][0] + bt0, 0.f) * wp0 + fmaxf(c[1][nh][1] + bt1, 0.f) * wp1;
            accR[1][1] += fmaxf(c[1][nh][2] + bt0, 0.f) * wp0 + fmaxf(c[1][nh][3] + bt1, 0.f) * wp1;
        }
    }
#pragma unroll
    for (int o = 1; o <= 2; o <<= 1) {
        accR[0][0] += __shfl_xor_sync(0xffffffffu, accR[0][0], o);
        accR[0][1] += __shfl_xor_sync(0xffffffffu, accR[0][1], o);
        accR[1][0] += __shfl_xor_sync(0xffffffffu, accR[1][0], o);
        accR[1][1] += __shfl_xor_sync(0xffffffffu, accR[1][1], o);
    }
    if ((lane & 3) == 0) {
        int g = lane >> 2;
        float bp = sc[512 + s];
#pragma unroll
        for (int mt = 0; mt < 2; mt++)
#pragma unroll
            for (int hh = 0; hh < 2; hh++) {
                int row = mrow0 + mt * 16 + hh * 8 + g;
                size_t p = (size_t)blockIdx.x * 128 + (size_t)row;
                float tp = accR[mt][hh] + bp;
                float lg = (tp >= 0.f) ? -log1pf(expf(-tp)) : tp - log1pf(expf(tp));
                g_twlog[(size_t)s * (LL * LL) + p] = lg;
            }
    }
}

// ---- in-tile LayerNorm of As[16][128] (256 thr, 16 per row) ----
__device__ __forceinline__ void tile_ln16(float* As, const float* __restrict__ g,
                                          const float* __restrict__ b, int tid,
                                          bool wb, float* __restrict__ dst, int r0) {
    int r = tid >> 4, t16 = tid & 15;
    float s = 0.f, s2 = 0.f;
#pragma unroll
    for (int j = 0; j < 8; j++) {
        float v = As[r * 128 + t16 * 8 + j];
        s += v; s2 += v * v;
    }
#pragma unroll
    for (int o = 1; o <= 8; o <<= 1) {
        s  += __shfl_xor_sync(0xffffffffu, s, o);
        s2 += __shfl_xor_sync(0xffffffffu, s2, o);
    }
    float m = s * (1.0f / DD);
    float var = s2 * (1.0f / DD) - m * m;
    float rin = rsqrtf(var + 1e-8f);
#pragma unroll
    for (int j = 0; j < 8; j++) {
        int c = t16 * 8 + j;
        float val = (As[r * 128 + c] - m) * rin * g[c] + b[c];
        As[r * 128 + c] = val;
        if (wb) dst[(r0 + r) * 128 + c] = val;
    }
    __syncthreads();
}

// ---------------- persistent fused tail kernel: 128 CTAs x 256 thr ----------
#define TAIL_SMEM (2 * 512 * 33 * 4)    // attn K+V staging (GEMM phases use a prefix)

__global__ void __launch_bounds__(256)
tail_kernel(const float* __restrict__ Wq, const float* __restrict__ bq,
            const float* __restrict__ Wk, const float* __restrict__ bk,
            const float* __restrict__ Wv, const float* __restrict__ bv,
            const float* __restrict__ ln1g, const float* __restrict__ ln1b,
            const float* __restrict__ ln2g, const float* __restrict__ ln2b,
            const float* __restrict__ W1, const float* __restrict__ b1,
            const float* __restrict__ W2, const float* __restrict__ b2,
            const float* __restrict__ lnfg, const float* __restrict__ lnfb,
            float* __restrict__ out) {
    extern __shared__ float fsm[];
    float* As = fsm;                 // 16*128
    float* Ws = fsm + 16 * 128;      // 128*32
    int cta = blockIdx.x, tid = threadIdx.x;
    int lane = tid & 31, w = tid >> 5;
    const float NEGV = -4294967295.0f;
    const float SCALE = 0.17677669529663689f;  // 1/sqrt(32)

    for (int i = 0; i < 2; i++) {
        const int wo = i * 16384, bo = i * 128;
        int r0 = (cta >> 2) * 16, c0 = (cta & 3) * 32;

        // ---- phase A: ln1 (z==0) + Q/K/V projections, 16x32 tiles ----
#pragma unroll 1
        for (int z = 0; z < 3; z++) {
            const float* W    = (z == 0) ? Wq + wo : (z == 1) ? Wk + wo : Wv + wo;
            const float* bias = (z == 0) ? bq + bo : (z == 1) ? bk + bo : bv + bo;
            float* C          = (z == 0) ? g_qp : (z == 1) ? g_kp : g_vp;
            for (int t = tid; t < 16 * 128; t += 256)
                As[t] = g_seq[(r0 + (t >> 7)) * 128 + (t & 127)];
            for (int t = tid; t < 128 * 32; t += 256)
                Ws[t] = W[(t >> 5) * 128 + c0 + (t & 31)];
            __syncthreads();
            if (z == 0) tile_ln16(As, ln1g + bo, ln1b + bo, tid, c0 == 0, g_Q, r0);
            float a0 = 0.f, a1 = 0.f;
            for (int k = 0; k < 128; k++) {
                float wv = Ws[k * 32 + lane];
                a0 += As[(w * 2) * 128 + k] * wv;
                a1 += As[(w * 2 + 1) * 128 + k] * wv;
            }
            float bb = bias[c0 + lane];
            C[(r0 + w * 2) * 128 + c0 + lane]     = a0 + bb;
            C[(r0 + w * 2 + 1) * 128 + c0 + lane] = a1 + bb;
            __syncthreads();
        }
        grid_barrier();

        // ---- phase B: attention (warp-per-q), CTA = (h, q-block of 16) ----
        {
            float* ks = fsm;
            float* vs = fsm + 512 * 33;
            int h = cta >> 5, q0 = (cta & 31) * 16;
            for (int t = tid; t < 512 * 32; t += 256) {
                int kk = t >> 5, d = t & 31;
                ks[kk * 33 + d] = g_kp[kk * 128 + h * 32 + d];
                vs[kk * 33 + d] = g_vp[kk * 128 + h * 32 + d];
            }
            __syncthreads();
            float* wout = out + 65536 + (size_t)i * 1048576;
            for (int qi = w; qi < 16; qi += 8) {
                int q = q0 + qi;
                float qreg[32];
                const float4* q4 = (const float4*)(g_qp + q * 128 + h * 32);
#pragma unroll
                for (int j = 0; j < 8; j++) {
                    float4 t4 = q4[j];
                    qreg[j * 4]     = t4.x; qreg[j * 4 + 1] = t4.y;
                    qreg[j * 4 + 2] = t4.z; qreg[j * 4 + 3] = t4.w;
                }
                bool padq = (g_keep[q] == 0.0f);
                const float* tw = g_twlog + (size_t)i * (LL * LL) + (size_t)q * 512;
                float sv[16];
                float mx = -3.4e38f;
#pragma unroll
                for (int blk = 0; blk < 16; blk++) {
                    int kk = blk * 32 + lane;
                    float dot = 0.f;
#pragma unroll
                    for (int d = 0; d < 32; d++) dot += qreg[d] * ks[kk * 33 + d];
                    float sva = (padq || kk > q) ? NEGV : (dot + tw[kk]) * SCALE;
                    sv[blk] = sva;
                    mx = fmaxf(mx, sva);
                }
#pragma unroll
                for (int o = 16; o; o >>= 1) mx = fmaxf(mx, __shfl_xor_sync(0xffffffffu, mx, o));
                float sum = 0.f;
#pragma unroll
                for (int blk = 0; blk < 16; blk++) {
                    float e = expf(sv[blk] - mx);
                    sv[blk] = e;
                    sum += e;
                }
#pragma unroll
                for (int o = 16; o; o >>= 1) sum += __shfl_xor_sync(0xffffffffu, sum, o);
                float inv = 1.0f / sum;
#pragma unroll
                for (int blk = 0; blk < 16; blk++) {
                    float wv = sv[blk] * inv;
                    sv[blk] = wv;
                    wout[(size_t)h * 262144 + (size_t)q * 512 + blk * 32 + lane] = wv;
                }
                float acc = 0.f;
#pragma unroll
                for (int blk = 0; blk < 16; blk++) {
#pragma unroll
                    for (int src = 0; src < 32; src++) {
                        float wv = __shfl_sync(0xffffffffu, sv[blk], src);
                        acc += wv * vs[(blk * 32 + src) * 33 + lane];
                    }
                }
                g_seq[q * 128 + h * 32 + lane] = g_Q[q * 128 + h * 32 + lane] + acc;
            }
            __syncthreads();
        }
        grid_barrier();

        // ---- phase C: ln2 + FFN1: relu(ln2(g_seq)@W1+b1) -> g_h ----
        {
            for (int t = tid; t < 16 * 128; t += 256)
                As[t] = g_seq[(r0 + (t >> 7)) * 128 + (t & 127)];
            for (int t = tid; t < 128 * 32; t += 256)
                Ws[t] = W1[wo + (t >> 5) * 128 + c0 + (t & 31)];
            __syncthreads();
            tile_ln16(As, ln2g + bo, ln2b + bo, tid, c0 == 0, g_x, r0);
            float a0 = 0.f, a1 = 0.f;
            for (int k = 0; k < 128; k++) {
                float wv = Ws[k * 32 + lane];
                a0 += As[(w * 2) * 128 + k] * wv;
                a1 += As[(w * 2 + 1) * 128 + k] * wv;
            }
            float bb = b1[bo + c0 + lane];
            g_h[(r0 + w * 2) * 128 + c0 + lane]     = fmaxf(a0 + bb, 0.f);
            g_h[(r0 + w * 2 + 1) * 128 + c0 + lane] = fmaxf(a1 + bb, 0.f);
            __syncthreads();
        }
        grid_barrier();

        // ---- phase D: FFN2: (g_x + g_h@W2+b2)*keep -> g_seq ----
        {
            for (int t = tid; t < 16 * 128; t += 256)
                As[t] = g_h[(r0 + (t >> 7)) * 128 + (t & 127)];
            for (int t = tid; t < 128 * 32; t += 256)
                Ws[t] = W2[wo + (t >> 5) * 128 + c0 + (t & 31)];
            __syncthreads();
            float a0 = 0.f, a1 = 0.f;
            for (int k = 0; k < 128; k++) {
                float wv = Ws[k * 32 + lane];
                a0 += As[(w * 2) * 128 + k] * wv;
                a1 += As[(w * 2 + 1) * 128 + k] * wv;
            }
            float bb = b2[bo + c0 + lane];
            int row0 = r0 + w * 2, row1 = row0 + 1;
            g_seq[row0 * 128 + c0 + lane] =
                (g_x[row0 * 128 + c0 + lane] + a0 + bb) * g_keep[row0];
            g_seq[row1 * 128 + c0 + lane] =
                (g_x[row1 * 128 + c0 + lane] + a1 + bb) * g_keep[row1];
            __syncthreads();
        }
        grid_barrier();
    }

    // ---- final LayerNorm: warp-per-row ----
    if (w < 4) {
        int row = cta * 4 + w;
        const float4* sr = (const float4*)(g_seq + row * 128);
        float4 xv = sr[lane];
        float s = xv.x + xv.y + xv.z + xv.w;
        float s2 = xv.x * xv.x + xv.y * xv.y + xv.z * xv.z + xv.w * xv.w;
#pragma unroll
        for (int o = 16; o; o >>= 1) {
            s  += __shfl_xor_sync(0xffffffffu, s, o);
            s2 += __shfl_xor_sync(0xffffffffu, s2, o);
        }
        float m = s * (1.0f / DD);
        float var = s2 * (1.0f / DD) - m * m;
        float rin = rsqrtf(var + 1e-8f);
        float4 gv = ((const float4*)lnfg)[lane];
        float4 bv4 = ((const float4*)lnfb)[lane];
        float4 o4;
        o4.x = (xv.x - m) * rin * gv.x + bv4.x;
        o4.y = (xv.y - m) * rin * gv.y + bv4.y;
        o4.z = (xv.z - m) * rin * gv.z + bv4.z;
        o4.w = (xv.w - m) * rin * gv.w + bv4.w;
        ((float4*)(out + row * 128))[lane] = o4;
    }
}

// ---------------- launch ----------------
extern "C" void kernel_launch(void* const* d_in, const int* in_sizes, int n_in,
                              void* d_out, int out_size) {
    const int*   logs = (const int*)d_in[0];
    const float* seqs = (const float*)d_in[1];
    const float* tmk  = (const float*)d_in[2];
    const float* Wq   = (const float*)d_in[3];
    const float* bq   = (const float*)d_in[4];
    const float* Wk   = (const float*)d_in[5];
    const float* bk   = (const float*)d_in[6];
    const float* Wv   = (const float*)d_in[7];
    const float* bv   = (const float*)d_in[8];
    const float* Wt   = (const float*)d_in[9];
    const float* bt   = (const float*)d_in[10];
    const float* Wtp  = (const float*)d_in[11];
    const float* btp  = (const float*)d_in[12];
    const float* ln1g = (const float*)d_in[13];
    const float* ln1b = (const float*)d_in[14];
    const float* ln2g = (const float*)d_in[15];
    const float* ln2b = (const float*)d_in[16];
    const float* W1   = (const float*)d_in[17];
    const float* b1   = (const float*)d_in[18];
    const float* W2   = (const float*)d_in[19];
    const float* b2   = (const float*)d_in[20];
    const float* lnfg = (const float*)d_in[21];
    const float* lnfb = (const float*)d_in[22];
    float* out = (float*)d_out;

    cudaFuncSetAttribute(twbias_kernel, cudaFuncAttributeMaxDynamicSharedMemorySize, TW_SMEM);
    cudaFuncSetAttribute(tail_kernel, cudaFuncAttributeMaxDynamicSharedMemorySize, TAIL_SMEM);

    prep_all_kernel<<<256, 256>>>(logs, seqs, Wt);
    twbias_kernel<<<2048, 256, TW_SMEM>>>(tmk, bt, Wtp, btp);
    tail_kernel<<<NCTA, 256, TAIL_SMEM>>>(Wq, bq, Wk, bk, Wv, bv, ln1g, ln1b,
                                          ln2g, ln2b, W1, b1, W2, b2, lnfg, lnfb, out);
}

// round 9
// speedup vs baseline: 1.1754x; 1.1754x over previous
#include <cuda_runtime.h>
#include <cuda_bf16.h>
#include <cstdint>

#define LL 512
#define DD 128
#define NCTA 128

// ---------------- scratch globals ----------------
__device__ float g_keep[LL];
__device__ float g_seq[LL * DD];
__device__ float g_Q[LL * DD];
__device__ float g_qp[LL * DD];
__device__ float g_kp[LL * DD];
__device__ float g_vp[LL * DD];
__device__ float g_twlog[2 * LL * LL];
__device__ __nv_bfloat16 g_Bimg[2 * 128 * 128];  // [s][n][k] = Wt[s][k][n]

__device__ unsigned g_bar_count;
__device__ volatile unsigned g_bar_gen;

__device__ __forceinline__ void grid_barrier() {
    __syncthreads();
    if (threadIdx.x == 0) {
        __threadfence();
        unsigned gen = g_bar_gen;
        if (atomicAdd(&g_bar_count, 1u) == NCTA - 1) {
            atomicExch(&g_bar_count, 0u);
            __threadfence();
            g_bar_gen = gen + 1u;
        } else {
            while (g_bar_gen == gen) __nanosleep(32);
        }
        __threadfence();
    }
    __syncthreads();
}

__device__ __forceinline__ uint32_t smem_to_u32(const void* p) {
    uint32_t a;
    asm("{ .reg .u64 t; cvta.to.shared.u64 t, %1; cvt.u32.u64 %0, t; }" : "=r"(a) : "l"(p));
    return a;
}
__device__ __forceinline__ void ldmatrix_x4(uint32_t* r, uint32_t addr) {
    asm volatile("ldmatrix.sync.aligned.m8n8.x4.shared.b16 {%0,%1,%2,%3}, [%4];"
                 : "=r"(r[0]), "=r"(r[1]), "=r"(r[2]), "=r"(r[3]) : "r"(addr));
}
__device__ __forceinline__ void mma16816(float* c, const uint32_t* a, uint32_t b0, uint32_t b1) {
    asm volatile(
        "mma.sync.aligned.m16n8k16.row.col.f32.bf16.bf16.f32 "
        "{%0,%1,%2,%3}, {%4,%5,%6,%7}, {%8,%9}, {%0,%1,%2,%3};"
        : "+f"(c[0]), "+f"(c[1]), "+f"(c[2]), "+f"(c[3])
        : "r"(a[0]), "r"(a[1]), "r"(a[2]), "r"(a[3]), "r"(b0), "r"(b1));
}

// ---------------- prep: keep + masked seqs + B images, one kernel -----------
__global__ void prep_all_kernel(const int* __restrict__ logs, const float* __restrict__ seqs,
                                const float* __restrict__ Wt) {
    int i = blockIdx.x * 256 + threadIdx.x;  // 65536
    if (i < LL) g_keep[i] = (logs[i] == 0) ? 0.0f : 1.0f;
    int row = i >> 7;
    float k = (logs[row] == 0) ? 0.0f : 1.0f;
    g_seq[i] = seqs[i] * k;
    if (i < 32768) {
        int s = i >> 14, e = i & 16383;
        int n = e >> 7, kk = e & 127;
        g_Bimg[i] = __float2bfloat16(Wt[s * 16384 + kk * 128 + n]);
    }
}

// ---------------- big fused time-bias kernel (unchanged from R6/R8) ---------
#define TW_SA   0
#define TW_SB   34816
#define TW_SSC  (TW_SB + 2 * 34816)      // 104448
#define TW_SMEM (TW_SSC + 2064)          // 106512

__global__ void __launch_bounds__(256, 2)
twbias_kernel(const float* __restrict__ T, const float* __restrict__ bt,
              const float* __restrict__ Wtp, const float* __restrict__ btp) {
    extern __shared__ char smem[];
    uint32_t sb = smem_to_u32(smem);
    int tid = threadIdx.x;
    float* sc = (float*)(smem + TW_SSC);

    {   // stage B images (padded rows, 272B stride)
        const uint4* src = (const uint4*)g_Bimg;
        for (int i = tid; i < 4096; i += 256) {
            int e = i * 8;
            int s = e >> 14, n = (e >> 7) & 127, k = e & 127;
            *(uint4*)(smem + TW_SB + s * 34816 + n * 272 + k * 2) = src[i];
        }
    }
    if (tid < 128) {
        sc[tid]       = bt[tid];
        sc[128 + tid] = bt[128 + tid];
        sc[256 + tid] = Wtp[tid];
        sc[384 + tid] = Wtp[128 + tid];
    }
    if (tid == 0) { sc[512] = btp[0]; sc[513] = btp[1]; }

    {   // A tile: 128 rows x 128 fp32 -> bf16, stride 272B
        size_t r0 = (size_t)blockIdx.x * 128;
        const float4* Tb = (const float4*)(T + r0 * 128);
#pragma unroll
        for (int i = 0; i < 16; i++) {
            int c = tid + 256 * i;
            int r = c >> 5, kc = (c & 31) << 2;
            float4 a = Tb[c];
            __nv_bfloat162 lo = __floats2bfloat162_rn(a.x, a.y);
            __nv_bfloat162 hi = __floats2bfloat162_rn(a.z, a.w);
            uint2 u;
            u.x = *reinterpret_cast<uint32_t*>(&lo);
            u.y = *reinterpret_cast<uint32_t*>(&hi);
            *(uint2*)(smem + TW_SA + r * 272 + kc * 2) = u;
        }
    }
    __syncthreads();

    int lane = tid & 31, w = tid >> 5;
    int s = w >> 2, mrow0 = (w & 3) * 32;
    int l8 = lane & 7, gq = lane >> 3;
    int arow = (gq & 1) * 8 + l8;
    int akoff = (gq >> 1) * 8;

    uint32_t a[2][8][4];
#pragma unroll
    for (int mt = 0; mt < 2; mt++)
#pragma unroll
        for (int kt = 0; kt < 8; kt++) {
            uint32_t addr = sb + TW_SA + (uint32_t)(mrow0 + mt * 16 + arow) * 272
                          + (uint32_t)(kt * 16 + akoff) * 2;
            ldmatrix_x4(a[mt][kt], addr);
        }

    int bntl = gq >> 1;
    int bkoff = (gq & 1) * 8;
    uint32_t b_base = sb + TW_SB + (uint32_t)s * 34816;
    int qd = lane & 3;

    float accR[2][2] = {{0.f, 0.f}, {0.f, 0.f}};
#pragma unroll
    for (int ntp = 0; ntp < 8; ntp++) {
        float c[2][2][4];
#pragma unroll
        for (int i = 0; i < 2; i++)
#pragma unroll
            for (int j = 0; j < 2; j++)
#pragma unroll
                for (int t = 0; t < 4; t++) c[i][j][t] = 0.f;
#pragma unroll
        for (int kt = 0; kt < 8; kt++) {
            uint32_t baddr = b_base + (uint32_t)(ntp * 16 + bntl * 8 + l8) * 272
                           + (uint32_t)(kt * 16 + bkoff) * 2;
            uint32_t b[4];
            ldmatrix_x4(b, baddr);
            mma16816(c[0][0], a[0][kt], b[0], b[1]);
            mma16816(c[0][1], a[0][kt], b[2], b[3]);
            mma16816(c[1][0], a[1][kt], b[0], b[1]);
            mma16816(c[1][1], a[1][kt], b[2], b[3]);
        }
#pragma unroll
        for (int nh = 0; nh < 2; nh++) {
            int n0 = (ntp * 2 + nh) * 8 + 2 * qd;
            float bt0 = sc[s * 128 + n0],       bt1 = sc[s * 128 + n0 + 1];
            float wp0 = sc[256 + s * 128 + n0], wp1 = sc[256 + s * 128 + n0 + 1];
            accR[0][0] += fmaxf(c[0][nh][0] + bt0, 0.f) * wp0 + fmaxf(c[0][nh][1] + bt1, 0.f) * wp1;
            accR[0][1] += fmaxf(c[0][nh][2] + bt0, 0.f) * wp0 + fmaxf(c[0][nh][3] + bt1, 0.f) * wp1;
            accR[1][0] += fmaxf(c[1][nh][0] + bt0, 0.f) * wp0 + fmaxf(c[1][nh][1] + bt1, 0.f) * wp1;
            accR[1][1] += fmaxf(c[1][nh][2] + bt0, 0.f) * wp0 + fmaxf(c[1][nh][3] + bt1, 0.f) * wp1;
        }
    }
#pragma unroll
    for (int o = 1; o <= 2; o <<= 1) {
        accR[0][0] += __shfl_xor_sync(0xffffffffu, accR[0][0], o);
        accR[0][1] += __shfl_xor_sync(0xffffffffu, accR[0][1], o);
        accR[1][0] += __shfl_xor_sync(0xffffffffu, accR[1][0], o);
        accR[1][1] += __shfl_xor_sync(0xffffffffu, accR[1][1], o);
    }
    if ((lane & 3) == 0) {
        int g = lane >> 2;
        float bp = sc[512 + s];
#pragma unroll
        for (int mt = 0; mt < 2; mt++)
#pragma unroll
            for (int hh = 0; hh < 2; hh++) {
                int row = mrow0 + mt * 16 + hh * 8 + g;
                size_t p = (size_t)blockIdx.x * 128 + (size_t)row;
                float tp = accR[mt][hh] + bp;
                float lg = (tp >= 0.f) ? -log1pf(expf(-tp)) : tp - log1pf(expf(tp));
                g_twlog[(size_t)s * (LL * LL) + p] = lg;
            }
    }
}

// ---------------- persistent fused tail v2: 128 CTAs x 512 thr --------------
// smem layout (floats):
//   GEMM phases: [0..511] rows_raw, [512..1023] rows_ln(x), [1024..1535] h,
//                [1536..1551] ln stats, [2048..18431] Ws (128x128)
//   attn phase:  [0 .. 512*33) ks, [512*33 .. 2*512*33) vs   (clobbers all)
#define TAIL_SMEM (2 * 512 * 33 * 4)    // 135168 B

// warp-cooperative row LN stats: warps 0-3 reduce rows 0-3 of rowbuf[4][128]
__device__ __forceinline__ void row_stats(const float* rowbuf, float* stats,
                                          int w, int lane) {
    if (w < 4) {
        float s = 0.f, s2 = 0.f;
#pragma unroll
        for (int j = 0; j < 4; j++) {
            float v = rowbuf[w * 128 + lane + 32 * j];
            s += v; s2 += v * v;
        }
#pragma unroll
        for (int o = 16; o; o >>= 1) {
            s  += __shfl_xor_sync(0xffffffffu, s, o);
            s2 += __shfl_xor_sync(0xffffffffu, s2, o);
        }
        if (lane == 0) {
            float m = s * (1.0f / DD);
            float var = s2 * (1.0f / DD) - m * m;
            stats[w * 2]     = m;
            stats[w * 2 + 1] = rsqrtf(var + 1e-8f);
        }
    }
    __syncthreads();
}

__global__ void __launch_bounds__(512)
tail_kernel(const float* __restrict__ Wq, const float* __restrict__ bq,
            const float* __restrict__ Wk, const float* __restrict__ bk,
            const float* __restrict__ Wv, const float* __restrict__ bv,
            const float* __restrict__ ln1g, const float* __restrict__ ln1b,
            const float* __restrict__ ln2g, const float* __restrict__ ln2b,
            const float* __restrict__ W1, const float* __restrict__ b1,
            const float* __restrict__ W2, const float* __restrict__ b2,
            const float* __restrict__ lnfg, const float* __restrict__ lnfb,
            float* __restrict__ out) {
    extern __shared__ float fsm[];
    float* rows_raw = fsm;
    float* rows_ln  = fsm + 512;
    float* hbuf     = fsm + 1024;
    float* stats    = fsm + 1536;
    float* Ws       = fsm + 2048;

    int cta = blockIdx.x, tid = threadIdx.x;
    int lane = tid & 31, w = tid >> 5;
    int r0 = cta * 4;
    int trow = tid >> 7, tcol = tid & 127;
    const float NEGV = -4294967295.0f;
    const float SCALE = 0.17677669529663689f;  // 1/sqrt(32)

    for (int i = 0; i < 2; i++) {
        const int wo = i * 16384, bo = i * 128;

        // ======== phase A: ln1 + Q/K/V for own 4 rows ========
        rows_raw[tid] = g_seq[(r0 + trow) * 128 + tcol];
        __syncthreads();
        row_stats(rows_raw, stats, w, lane);
        {
            float m = stats[trow * 2], rinv = stats[trow * 2 + 1];
            float val = (rows_raw[tid] - m) * rinv * ln1g[bo + tcol] + ln1b[bo + tcol];
            rows_ln[tid] = val;
            g_Q[(r0 + trow) * 128 + tcol] = val;
        }
        __syncthreads();
#pragma unroll 1
        for (int z = 0; z < 3; z++) {
            const float* W    = (z == 0) ? Wq + wo : (z == 1) ? Wk + wo : Wv + wo;
            const float* bias = (z == 0) ? bq + bo : (z == 1) ? bk + bo : bv + bo;
            float* C          = (z == 0) ? g_qp : (z == 1) ? g_kp : g_vp;
            const float4* Wsrc = (const float4*)W;
            float4* Wdst = (float4*)Ws;
#pragma unroll
            for (int j = 0; j < 8; j++) Wdst[tid + 512 * j] = Wsrc[tid + 512 * j];
            __syncthreads();
            const float* src = (z == 0) ? rows_ln : rows_raw;
            float a0 = 0.f, a1 = 0.f, a2 = 0.f, a3 = 0.f;
#pragma unroll
            for (int k = 0; k < 128; k += 4) {
                a0 += src[trow * 128 + k]     * Ws[(k) * 128 + tcol];
                a1 += src[trow * 128 + k + 1] * Ws[(k + 1) * 128 + tcol];
                a2 += src[trow * 128 + k + 2] * Ws[(k + 2) * 128 + tcol];
                a3 += src[trow * 128 + k + 3] * Ws[(k + 3) * 128 + tcol];
            }
            C[(r0 + trow) * 128 + tcol] = (a0 + a1) + (a2 + a3) + bias[tcol];
            __syncthreads();
        }
        grid_barrier();

        // ======== phase B: attention, CTA=(h, q-chunk of 16), warp-per-q ====
        {
            float* ks = fsm;
            float* vs = fsm + 512 * 33;
            int h = cta >> 5, q0 = (cta & 31) * 16;
            for (int t = tid; t < 512 * 32; t += 512) {
                int kk = t >> 5, d = t & 31;
                ks[kk * 33 + d] = g_kp[kk * 128 + h * 32 + d];
                vs[kk * 33 + d] = g_vp[kk * 128 + h * 32 + d];
            }
            __syncthreads();
            float* wout = out + 65536 + (size_t)i * 1048576;
            int q = q0 + w;
            float qreg[32];
            const float4* q4 = (const float4*)(g_qp + q * 128 + h * 32);
#pragma unroll
            for (int j = 0; j < 8; j++) {
                float4 t4 = q4[j];
                qreg[j * 4]     = t4.x; qreg[j * 4 + 1] = t4.y;
                qreg[j * 4 + 2] = t4.z; qreg[j * 4 + 3] = t4.w;
            }
            bool padq = (g_keep[q] == 0.0f);
            const float* tw = g_twlog + (size_t)i * (LL * LL) + (size_t)q * 512;
            float sv[16];
            float mx = -3.4e38f;
#pragma unroll
            for (int blk = 0; blk < 16; blk++) {
                int kk = blk * 32 + lane;
                float d0 = 0.f, d1 = 0.f;
#pragma unroll
                for (int d = 0; d < 32; d += 2) {
                    d0 += qreg[d]     * ks[kk * 33 + d];
                    d1 += qreg[d + 1] * ks[kk * 33 + d + 1];
                }
                float sva = (padq || kk > q) ? NEGV : ((d0 + d1) + tw[kk]) * SCALE;
                sv[blk] = sva;
                mx = fmaxf(mx, sva);
            }
#pragma unroll
            for (int o = 16; o; o >>= 1) mx = fmaxf(mx, __shfl_xor_sync(0xffffffffu, mx, o));
            float sum = 0.f;
#pragma unroll
            for (int blk = 0; blk < 16; blk++) {
                float e = expf(sv[blk] - mx);
                sv[blk] = e;
                sum += e;
            }
#pragma unroll
            for (int o = 16; o; o >>= 1) sum += __shfl_xor_sync(0xffffffffu, sum, o);
            float inv = 1.0f / sum;
#pragma unroll
            for (int blk = 0; blk < 16; blk++) {
                float wv = sv[blk] * inv;
                sv[blk] = wv;
                wout[(size_t)h * 262144 + (size_t)q * 512 + blk * 32 + lane] = wv;
            }
            float ac0 = 0.f, ac1 = 0.f, ac2 = 0.f, ac3 = 0.f;
#pragma unroll
            for (int blk = 0; blk < 16; blk++) {
#pragma unroll
                for (int src = 0; src < 32; src += 4) {
                    ac0 += __shfl_sync(0xffffffffu, sv[blk], src)     * vs[(blk * 32 + src) * 33 + lane];
                    ac1 += __shfl_sync(0xffffffffu, sv[blk], src + 1) * vs[(blk * 32 + src + 1) * 33 + lane];
                    ac2 += __shfl_sync(0xffffffffu, sv[blk], src + 2) * vs[(blk * 32 + src + 2) * 33 + lane];
                    ac3 += __shfl_sync(0xffffffffu, sv[blk], src + 3) * vs[(blk * 32 + src + 3) * 33 + lane];
                }
            }
            float acc = (ac0 + ac1) + (ac2 + ac3);
            g_seq[q * 128 + h * 32 + lane] = g_Q[q * 128 + h * 32 + lane] + acc;
            __syncthreads();
        }
        grid_barrier();

        // ======== phase C: ln2 + FFN1 (own rows, h kept in smem) ========
        rows_raw[tid] = g_seq[(r0 + trow) * 128 + tcol];
        __syncthreads();
        row_stats(rows_raw, stats, w, lane);
        {
            float m = stats[trow * 2], rinv = stats[trow * 2 + 1];
            rows_ln[tid] = (rows_raw[tid] - m) * rinv * ln2g[bo + tcol] + ln2b[bo + tcol];
        }
        __syncthreads();
        {
            const float4* Wsrc = (const float4*)(W1 + wo);
            float4* Wdst = (float4*)Ws;
#pragma unroll
            for (int j = 0; j < 8; j++) Wdst[tid + 512 * j] = Wsrc[tid + 512 * j];
            __syncthreads();
            float a0 = 0.f, a1 = 0.f, a2 = 0.f, a3 = 0.f;
#pragma unroll
            for (int k = 0; k < 128; k += 4) {
                a0 += rows_ln[trow * 128 + k]     * Ws[(k) * 128 + tcol];
                a1 += rows_ln[trow * 128 + k + 1] * Ws[(k + 1) * 128 + tcol];
                a2 += rows_ln[trow * 128 + k + 2] * Ws[(k + 2) * 128 + tcol];
                a3 += rows_ln[trow * 128 + k + 3] * Ws[(k + 3) * 128 + tcol];
            }
            hbuf[tid] = fmaxf((a0 + a1) + (a2 + a3) + b1[bo + tcol], 0.f);
            __syncthreads();
        }
        // ======== phase D: FFN2 (local) ========
        {
            const float4* Wsrc = (const float4*)(W2 + wo);
            float4* Wdst = (float4*)Ws;
#pragma unroll
            for (int j = 0; j < 8; j++) Wdst[tid + 512 * j] = Wsrc[tid + 512 * j];
            __syncthreads();
            float a0 = 0.f, a1 = 0.f, a2 = 0.f, a3 = 0.f;
#pragma unroll
            for (int k = 0; k < 128; k += 4) {
                a0 += hbuf[trow * 128 + k]     * Ws[(k) * 128 + tcol];
                a1 += hbuf[trow * 128 + k + 1] * Ws[(k + 1) * 128 + tcol];
                a2 += hbuf[trow * 128 + k + 2] * Ws[(k + 2) * 128 + tcol];
                a3 += hbuf[trow * 128 + k + 3] * Ws[(k + 3) * 128 + tcol];
            }
            float y = (a0 + a1) + (a2 + a3) + b2[bo + tcol];
            g_seq[(r0 + trow) * 128 + tcol] =
                (rows_ln[tid] + y) * g_keep[r0 + trow];
            __syncthreads();
        }
        // no grid barrier: next phase A / lnf reads only own rows
    }

    // ======== final LayerNorm (own rows) ========
    rows_raw[tid] = g_seq[(r0 + trow) * 128 + tcol];
    __syncthreads();
    row_stats(rows_raw, stats, w, lane);
    {
        float m = stats[trow * 2], rinv = stats[trow * 2 + 1];
        out[(r0 + trow) * 128 + tcol] =
            (rows_raw[tid] - m) * rinv * lnfg[tcol] + lnfb[tcol];
    }
}

// ---------------- launch ----------------
extern "C" void kernel_launch(void* const* d_in, const int* in_sizes, int n_in,
                              void* d_out, int out_size) {
    const int*   logs = (const int*)d_in[0];
    const float* seqs = (const float*)d_in[1];
    const float* tmk  = (const float*)d_in[2];
    const float* Wq   = (const float*)d_in[3];
    const float* bq   = (const float*)d_in[4];
    const float* Wk   = (const float*)d_in[5];
    const float* bk   = (const float*)d_in[6];
    const float* Wv   = (const float*)d_in[7];
    const float* bv   = (const float*)d_in[8];
    const float* Wt   = (const float*)d_in[9];
    const float* bt   = (const float*)d_in[10];
    const float* Wtp  = (const float*)d_in[11];
    const float* btp  = (const float*)d_in[12];
    const float* ln1g = (const float*)d_in[13];
    const float* ln1b = (const float*)d_in[14];
    const float* ln2g = (const float*)d_in[15];
    const float* ln2b = (const float*)d_in[16];
    const float* W1   = (const float*)d_in[17];
    const float* b1   = (const float*)d_in[18];
    const float* W2   = (const float*)d_in[19];
    const float* b2   = (const float*)d_in[20];
    const float* lnfg = (const float*)d_in[21];
    const float* lnfb = (const float*)d_in[22];
    float* out = (float*)d_out;

    cudaFuncSetAttribute(twbias_kernel, cudaFuncAttributeMaxDynamicSharedMemorySize, TW_SMEM);
    cudaFuncSetAttribute(tail_kernel, cudaFuncAttributeMaxDynamicSharedMemorySize, TAIL_SMEM);

    prep_all_kernel<<<256, 256>>>(logs, seqs, Wt);
    twbias_kernel<<<2048, 256, TW_SMEM>>>(tmk, bt, Wtp, btp);
    tail_kernel<<<NCTA, 512, TAIL_SMEM>>>(Wq, bq, Wk, bk, Wv, bv, ln1g, ln1b,
                                          ln2g, ln2b, W1, b1, W2, b2, lnfg, lnfb, out);
}